// round 12
// baseline (speedup 1.0000x reference)
#include <cuda_runtime.h>
#include <cuda_bf16.h>
#include <cstdint>

#define DIM      256
#define TWO_DIM  512
#define KMAX     64
#define B_MAX    16384
#define NMT      (B_MAX / 16)      // 1024 m-frag-tiles
#define NKT      (DIM / 16)        // 16 k-frag-tiles
#define NNT      (TWO_DIM / 8)     // 64 n-frag-tiles

// ---------------- scratch (__device__ globals: allocation-guard-safe) ----------
__device__ __align__(16) uint32_t g_Afh[NMT * NKT * 32 * 4];
__device__ __align__(16) uint32_t g_Afl[NMT * NKT * 32 * 4];
__device__ __align__(16) uint32_t g_Wfh[NNT * NKT * 32 * 2];
__device__ __align__(16) uint32_t g_Wfl[NNT * NKT * 32 * 2];
__device__ __align__(128) float   g_H[B_MAX * TWO_DIM];

// ---------------- helpers ------------------------------------------------------
__device__ __forceinline__ uint32_t pack_bf16x2(float x0, float x1) {
    __nv_bfloat162 h = __floats2bfloat162_rn(x0, x1);
    return *reinterpret_cast<uint32_t*>(&h);
}
__device__ __forceinline__ void mma_bf16(float (&c)[4], const uint32_t* a,
                                         const uint32_t* b) {
    asm volatile("mma.sync.aligned.m16n8k16.row.col.f32.bf16.bf16.f32 "
                 "{%0,%1,%2,%3}, {%4,%5,%6,%7}, {%8,%9}, {%0,%1,%2,%3};"
                 : "+f"(c[0]), "+f"(c[1]), "+f"(c[2]), "+f"(c[3])
                 : "r"(a[0]), "r"(a[1]), "r"(a[2]), "r"(a[3]), "r"(b[0]), "r"(b[1]));
}

// ---------------- Kernel 1a: W -> B-operand fragments (hi/lo) ------------------
__global__ __launch_bounds__(256)
void conv_w(const float* __restrict__ W) {
    const int l   = threadIdx.x & 31;
    const int wid = threadIdx.x >> 5;
    const int nt  = blockIdx.x >> 1;
    const int kt  = ((blockIdx.x & 1) << 3) + wid;
    const int n   = nt * 8 + (l >> 2);
    uint2 hi, lo;
    #pragma unroll
    for (int r = 0; r < 2; r++) {
        const int k = kt * 16 + ((l & 3) << 1) + (r << 3);
        const float x0 = W[(size_t)k * TWO_DIM + n];
        const float x1 = W[(size_t)(k + 1) * TWO_DIM + n];
        const float h0 = __bfloat162float(__float2bfloat16_rn(x0));
        const float h1 = __bfloat162float(__float2bfloat16_rn(x1));
        (&hi.x)[r] = pack_bf16x2(x0, x1);
        (&lo.x)[r] = pack_bf16x2(x0 - h0, x1 - h1);
    }
    const size_t idx = ((size_t)nt * NKT + kt) * 32 + l;
    reinterpret_cast<uint2*>(g_Wfh)[idx] = hi;
    reinterpret_cast<uint2*>(g_Wfl)[idx] = lo;
}

// ---------------- Kernel 1b: gather v2e[nodes_v] -> A fragments (hi/lo) --------
__global__ __launch_bounds__(256)
void conv_a(const int* __restrict__ nodes_v, const float* __restrict__ v2e, int B) {
    const int mt  = blockIdx.x;
    const int l   = threadIdx.x & 31;
    const int wid = threadIdx.x >> 5;
    // two candidate source rows for this lane (row, row+8), fetched once
    const int row0 = (l >> 2);
    int b0 = mt * 16 + row0;     if (b0 >= B) b0 = B - 1;
    int b1 = mt * 16 + row0 + 8; if (b1 >= B) b1 = B - 1;
    const size_t v0 = (size_t)nodes_v[b0] * DIM;
    const size_t v1 = (size_t)nodes_v[b1] * DIM;
    #pragma unroll 1
    for (int kt = wid; kt < NKT; kt += 8) {
        uint4 hi, lo;
        #pragma unroll
        for (int r = 0; r < 4; r++) {
            const int col = kt * 16 + ((l & 3) << 1) + ((r & 2) << 2);
            const size_t base = (r & 1) ? v1 : v0;
            const float x0 = v2e[base + col];
            const float x1 = v2e[base + col + 1];
            const float h0 = __bfloat162float(__float2bfloat16_rn(x0));
            const float h1 = __bfloat162float(__float2bfloat16_rn(x1));
            (&hi.x)[r] = pack_bf16x2(x0, x1);
            (&lo.x)[r] = pack_bf16x2(x0 - h0, x1 - h1);
        }
        const size_t idx = ((size_t)mt * NKT + kt) * 32 + l;
        reinterpret_cast<uint4*>(g_Afh)[idx] = hi;
        reinterpret_cast<uint4*>(g_Afl)[idx] = lo;
    }
}

// ---------------- Kernel 2: H = A @ Wt^T, frag-direct (no smem, no syncs) ------
__global__ __launch_bounds__(256)
void gemm_mma(int B) {
    const int t   = threadIdx.x;
    const int wid = t >> 5;
    const int lid = t & 31;
    const int wm  = wid & 3;
    const int wn  = wid >> 2;
    const int m0t = blockIdx.x * 8;
    const int n0t = blockIdx.y * 16;

    float acc[2][8][4];
    #pragma unroll
    for (int mf = 0; mf < 2; mf++)
        #pragma unroll
        for (int nf = 0; nf < 8; nf++)
            #pragma unroll
            for (int q = 0; q < 4; q++) acc[mf][nf][q] = 0.f;

    const uint4* Afh4 = reinterpret_cast<const uint4*>(g_Afh);
    const uint4* Afl4 = reinterpret_cast<const uint4*>(g_Afl);
    const uint2* Wfh2 = reinterpret_cast<const uint2*>(g_Wfh);
    const uint2* Wfl2 = reinterpret_cast<const uint2*>(g_Wfl);

    #pragma unroll 2
    for (int kt = 0; kt < NKT; kt++) {
        uint4 ah[2], al[2];
        #pragma unroll
        for (int mf = 0; mf < 2; mf++) {
            const size_t ai = ((size_t)(m0t + wm * 2 + mf) * NKT + kt) * 32 + lid;
            ah[mf] = Afh4[ai];
            al[mf] = Afl4[ai];
        }
        #pragma unroll
        for (int nf = 0; nf < 8; nf++) {
            const size_t bi = ((size_t)(n0t + wn * 8 + nf) * NKT + kt) * 32 + lid;
            const uint2 bh = Wfh2[bi];
            const uint2 bl = Wfl2[bi];
            #pragma unroll
            for (int mf = 0; mf < 2; mf++) {
                mma_bf16(acc[mf][nf], &ah[mf].x, &bh.x);
                mma_bf16(acc[mf][nf], &ah[mf].x, &bl.x);
                mma_bf16(acc[mf][nf], &al[mf].x, &bh.x);
            }
        }
    }

    const int rbase = blockIdx.x * 128 + wm * 32 + (lid >> 2);
    const int cbase = blockIdx.y * 128 + wn * 64 + (lid & 3) * 2;
    #pragma unroll
    for (int mf = 0; mf < 2; mf++) {
        #pragma unroll
        for (int nf = 0; nf < 8; nf++) {
            const int row = rbase + mf * 16;
            const int col = cbase + nf * 8;
            if (row < B)
                *reinterpret_cast<float2*>(&g_H[(size_t)row * TWO_DIM + col]) =
                    make_float2(acc[mf][nf][0], acc[mf][nf][1]);
            if (row + 8 < B)
                *reinterpret_cast<float2*>(&g_H[(size_t)(row + 8) * TWO_DIM + col]) =
                    make_float2(acc[mf][nf][2], acc[mf][nf][3]);
        }
    }
}

// ---------------- Kernel 3: combine — ONE row per 64-thread group --------------
#define RPB 4
#define NTH 256

__global__ __launch_bounds__(NTH)
void combine(const int* __restrict__ nodes_u,
             const int* __restrict__ nodes_v,
             const int* __restrict__ neighbors,
             const int* __restrict__ neighbor_counts,
             const float* __restrict__ u2e,
             const float* __restrict__ v2e,
             const float* __restrict__ bvec,
             float* __restrict__ out,
             int B)
{
    __shared__ int   snb[RPB][KMAX];
    __shared__ int   scnt[RPB], su[RPB], svi[RPB], sbrow[RPB];
    __shared__ float sred[RPB][2];

    const int t    = threadIdx.x;
    const int gi   = t >> 6;          // group 0..3 -> row gi
    const int gt   = t & 63;
    const int c4   = gt * 4;
    const int row0 = blockIdx.x * RPB;

    if (t < RPB * KMAX) {             // 256 threads stage all 256 indices
        int r = t >> 6, k = t & 63;
        int b = row0 + r; if (b >= B) b = B - 1;
        snb[r][k] = neighbors[(size_t)b * KMAX + k];
    }
    if (t < RPB) {
        int b = row0 + t; if (b >= B) b = B - 1;
        scnt[t]  = neighbor_counts[b];
        su[t]    = nodes_u[b];
        svi[t]   = nodes_v[b];
        sbrow[t] = b;
    }
    __syncthreads();

    const float4 b4 = *reinterpret_cast<const float4*>(&bvec[c4]);

    const int r   = gi;
    const int cnt = scnt[r];
    const float4 self4 = *reinterpret_cast<const float4*>(&u2e[(size_t)su[r]  * DIM + c4]);
    const float4 v4    = *reinterpret_cast<const float4*>(&v2e[(size_t)svi[r] * DIM + c4]);
    float partial;
    if (cnt > 0) {
        const size_t hb = (size_t)sbrow[r] * TWO_DIM;
        const float4 h1 = *reinterpret_cast<const float4*>(&g_H[hb + c4]);
        const float4 h2 = *reinterpret_cast<const float4*>(&g_H[hb + DIM + c4]);
        const int* nb = snb[r];
        float4 a0 = make_float4(0, 0, 0, 0), a1 = a0;
        int k = 0;
        #pragma unroll 1
        for (; k + 8 <= cnt; k += 8) {           // 8 independent 16B loads in flight
            float4 x0 = *reinterpret_cast<const float4*>(&u2e[(size_t)nb[k + 0] * DIM + c4]);
            float4 x1 = *reinterpret_cast<const float4*>(&u2e[(size_t)nb[k + 1] * DIM + c4]);
            float4 x2 = *reinterpret_cast<const float4*>(&u2e[(size_t)nb[k + 2] * DIM + c4]);
            float4 x3 = *reinterpret_cast<const float4*>(&u2e[(size_t)nb[k + 3] * DIM + c4]);
            float4 x4 = *reinterpret_cast<const float4*>(&u2e[(size_t)nb[k + 4] * DIM + c4]);
            float4 x5 = *reinterpret_cast<const float4*>(&u2e[(size_t)nb[k + 5] * DIM + c4]);
            float4 x6 = *reinterpret_cast<const float4*>(&u2e[(size_t)nb[k + 6] * DIM + c4]);
            float4 x7 = *reinterpret_cast<const float4*>(&u2e[(size_t)nb[k + 7] * DIM + c4]);
            a0.x += x0.x; a0.y += x0.y; a0.z += x0.z; a0.w += x0.w;
            a1.x += x1.x; a1.y += x1.y; a1.z += x1.z; a1.w += x1.w;
            a0.x += x2.x; a0.y += x2.y; a0.z += x2.z; a0.w += x2.w;
            a1.x += x3.x; a1.y += x3.y; a1.z += x3.z; a1.w += x3.w;
            a0.x += x4.x; a0.y += x4.y; a0.z += x4.z; a0.w += x4.w;
            a1.x += x5.x; a1.y += x5.y; a1.z += x5.z; a1.w += x5.w;
            a0.x += x6.x; a0.y += x6.y; a0.z += x6.z; a0.w += x6.w;
            a1.x += x7.x; a1.y += x7.y; a1.z += x7.z; a1.w += x7.w;
        }
        #pragma unroll 1
        for (; k < cnt; k++) {
            float4 x = *reinterpret_cast<const float4*>(&u2e[(size_t)nb[k] * DIM + c4]);
            a0.x += x.x; a0.y += x.y; a0.z += x.z; a0.w += x.w;
        }
        const float inv = 1.f / (float)cnt;
        float4 nm;
        nm.x = (a0.x + a1.x) * inv;
        nm.y = (a0.y + a1.y) * inv;
        nm.z = (a0.z + a1.z) * inv;
        nm.w = (a0.w + a1.w) * inv;
        partial = self4.x * h1.x + self4.y * h1.y + self4.z * h1.z + self4.w * h1.w
                + nm.x    * h2.x + nm.y    * h2.y + nm.z    * h2.z + nm.w    * h2.w
                + b4.x    * v4.x + b4.y    * v4.y + b4.z    * v4.z + b4.w    * v4.w;
    } else {
        partial = self4.x * v4.x + self4.y * v4.y + self4.z * v4.z + self4.w * v4.w;
    }
    #pragma unroll
    for (int o = 16; o; o >>= 1)
        partial += __shfl_down_sync(0xffffffffu, partial, o);
    if ((t & 31) == 0) sred[r][(t >> 5) & 1] = partial;
    __syncthreads();

    if (t < RPB) {
        float s = sred[t][0] + sred[t][1];
        if (row0 + t < B) out[row0 + t] = s;
    }
}

// ---------------- launch --------------------------------------------------------
extern "C" void kernel_launch(void* const* d_in, const int* in_sizes, int n_in,
                              void* d_out, int out_size)
{
    const int*   nodes_u         = (const int*)  d_in[0];
    const int*   nodes_v         = (const int*)  d_in[1];
    const int*   neighbors       = (const int*)  d_in[2];
    const int*   neighbor_counts = (const int*)  d_in[3];
    const float* u2e             = (const float*)d_in[4];
    const float* v2e             = (const float*)d_in[5];
    const float* W               = (const float*)d_in[6];
    const float* bvec            = (const float*)d_in[7];
    float*       out             = (float*)d_out;

    int B = in_sizes[0];
    if (B > B_MAX) B = B_MAX;
    const int nmt = (B + 15) / 16;

    conv_w<<<128, 256>>>(W);
    conv_a<<<nmt, 256>>>(nodes_v, v2e, B);
    dim3 ggrid((B + 127) / 128, TWO_DIM / 128);
    gemm_mma<<<ggrid, 256>>>(B);
    combine<<<(B + RPB - 1) / RPB, NTH>>>(nodes_u, nodes_v, neighbors, neighbor_counts,
                                          u2e, v2e, bvec, out, B);
}

// round 13
// speedup vs baseline: 1.0756x; 1.0756x over previous
#include <cuda_runtime.h>
#include <cuda_bf16.h>
#include <cstdint>

#define DIM      256
#define TWO_DIM  512
#define KMAX     64
#define B_MAX    16384
#define NMT      (B_MAX / 16)
#define NKT      (DIM / 16)
#define NNT      (TWO_DIM / 8)

// ---------------- scratch (__device__ globals: allocation-guard-safe) ----------
__device__ __align__(16) uint32_t g_Afh[NMT * NKT * 32 * 4];
__device__ __align__(16) uint32_t g_Afl[NMT * NKT * 32 * 4];
__device__ __align__(16) uint32_t g_Wfh[NNT * NKT * 32 * 2];
__device__ __align__(16) uint32_t g_Wfl[NNT * NKT * 32 * 2];
__device__ __align__(128) float   g_H[B_MAX * TWO_DIM];

// ---------------- helpers ------------------------------------------------------
__device__ __forceinline__ uint32_t pack_bf16x2(float x0, float x1) {
    __nv_bfloat162 h = __floats2bfloat162_rn(x0, x1);
    return *reinterpret_cast<uint32_t*>(&h);
}
__device__ __forceinline__ void mma_bf16(float (&c)[4], const uint32_t* a,
                                         const uint32_t* b) {
    asm volatile("mma.sync.aligned.m16n8k16.row.col.f32.bf16.bf16.f32 "
                 "{%0,%1,%2,%3}, {%4,%5,%6,%7}, {%8,%9}, {%0,%1,%2,%3};"
                 : "+f"(c[0]), "+f"(c[1]), "+f"(c[2]), "+f"(c[3])
                 : "r"(a[0]), "r"(a[1]), "r"(a[2]), "r"(a[3]), "r"(b[0]), "r"(b[1]));
}
__device__ __forceinline__ uint32_t smem_u32(const void* p) {
    uint32_t a;
    asm("{ .reg .u64 t; cvta.to.shared.u64 t, %1; cvt.u32.u64 %0, t; }" : "=r"(a) : "l"(p));
    return a;
}
#define CPA16(dst, src) \
    asm volatile("cp.async.cg.shared.global [%0], [%1], 16;" :: "r"(dst), "l"(src))
#define CPA_COMMIT() asm volatile("cp.async.commit_group;" ::: "memory")
#define CPA_WAIT(n)  asm volatile("cp.async.wait_group %0;" :: "n"(n) : "memory")

// ---------------- Kernel 1: fused conv (W frags + A frags) ---------------------
__global__ __launch_bounds__(256)
void conv_all(const float* __restrict__ W,
              const int* __restrict__ nodes_v, const float* __restrict__ v2e,
              int B, int nmt)
{
    if ((int)blockIdx.x >= nmt) {
        // ---- W -> B-operand fragments ----
        const int blk = blockIdx.x - nmt;          // 0..127
        const int l   = threadIdx.x & 31;
        const int wid = threadIdx.x >> 5;
        const int nt  = blk >> 1;
        const int kt  = ((blk & 1) << 3) + wid;
        const int n   = nt * 8 + (l >> 2);
        uint2 hi, lo;
        #pragma unroll
        for (int r = 0; r < 2; r++) {
            const int k = kt * 16 + ((l & 3) << 1) + (r << 3);
            const float x0 = W[(size_t)k * TWO_DIM + n];
            const float x1 = W[(size_t)(k + 1) * TWO_DIM + n];
            const float h0 = __bfloat162float(__float2bfloat16_rn(x0));
            const float h1 = __bfloat162float(__float2bfloat16_rn(x1));
            (&hi.x)[r] = pack_bf16x2(x0, x1);
            (&lo.x)[r] = pack_bf16x2(x0 - h0, x1 - h1);
        }
        const size_t idx = ((size_t)nt * NKT + kt) * 32 + l;
        reinterpret_cast<uint2*>(g_Wfh)[idx] = hi;
        reinterpret_cast<uint2*>(g_Wfl)[idx] = lo;
        return;
    }
    // ---- gather v2e[nodes_v] -> A fragments ----
    const int mt  = blockIdx.x;
    const int l   = threadIdx.x & 31;
    const int wid = threadIdx.x >> 5;
    const int row0 = (l >> 2);
    int b0 = mt * 16 + row0;     if (b0 >= B) b0 = B - 1;
    int b1 = mt * 16 + row0 + 8; if (b1 >= B) b1 = B - 1;
    const size_t v0 = (size_t)nodes_v[b0] * DIM;
    const size_t v1 = (size_t)nodes_v[b1] * DIM;
    #pragma unroll 1
    for (int kt = wid; kt < NKT; kt += 8) {
        uint4 hi, lo;
        #pragma unroll
        for (int r = 0; r < 4; r++) {
            const int col = kt * 16 + ((l & 3) << 1) + ((r & 2) << 2);
            const size_t base = (r & 1) ? v1 : v0;
            const float x0 = v2e[base + col];
            const float x1 = v2e[base + col + 1];
            const float h0 = __bfloat162float(__float2bfloat16_rn(x0));
            const float h1 = __bfloat162float(__float2bfloat16_rn(x1));
            (&hi.x)[r] = pack_bf16x2(x0, x1);
            (&lo.x)[r] = pack_bf16x2(x0 - h0, x1 - h1);
        }
        const size_t idx = ((size_t)mt * NKT + kt) * 32 + l;
        reinterpret_cast<uint4*>(g_Afh)[idx] = hi;
        reinterpret_cast<uint4*>(g_Afl)[idx] = lo;
    }
}

// ---------------- Kernel 2: H = A @ Wt^T, frag-direct --------------------------
__global__ __launch_bounds__(256)
void gemm_mma(int B) {
    const int t   = threadIdx.x;
    const int wid = t >> 5;
    const int lid = t & 31;
    const int wm  = wid & 3;
    const int wn  = wid >> 2;
    const int m0t = blockIdx.x * 8;
    const int n0t = blockIdx.y * 16;

    float acc[2][8][4];
    #pragma unroll
    for (int mf = 0; mf < 2; mf++)
        #pragma unroll
        for (int nf = 0; nf < 8; nf++)
            #pragma unroll
            for (int q = 0; q < 4; q++) acc[mf][nf][q] = 0.f;

    const uint4* Afh4 = reinterpret_cast<const uint4*>(g_Afh);
    const uint4* Afl4 = reinterpret_cast<const uint4*>(g_Afl);
    const uint2* Wfh2 = reinterpret_cast<const uint2*>(g_Wfh);
    const uint2* Wfl2 = reinterpret_cast<const uint2*>(g_Wfl);

    #pragma unroll 2
    for (int kt = 0; kt < NKT; kt++) {
        uint4 ah[2], al[2];
        #pragma unroll
        for (int mf = 0; mf < 2; mf++) {
            const size_t ai = ((size_t)(m0t + wm * 2 + mf) * NKT + kt) * 32 + lid;
            ah[mf] = Afh4[ai];
            al[mf] = Afl4[ai];
        }
        #pragma unroll
        for (int nf = 0; nf < 8; nf++) {
            const size_t bi = ((size_t)(n0t + wn * 8 + nf) * NKT + kt) * 32 + lid;
            const uint2 bh = Wfh2[bi];
            const uint2 bl = Wfl2[bi];
            #pragma unroll
            for (int mf = 0; mf < 2; mf++) {
                mma_bf16(acc[mf][nf], &ah[mf].x, &bh.x);
                mma_bf16(acc[mf][nf], &ah[mf].x, &bl.x);
                mma_bf16(acc[mf][nf], &al[mf].x, &bh.x);
            }
        }
    }

    const int rbase = blockIdx.x * 128 + wm * 32 + (lid >> 2);
    const int cbase = blockIdx.y * 128 + wn * 64 + (lid & 3) * 2;
    #pragma unroll
    for (int mf = 0; mf < 2; mf++) {
        #pragma unroll
        for (int nf = 0; nf < 8; nf++) {
            const int row = rbase + mf * 16;
            const int col = cbase + nf * 8;
            if (row < B)
                *reinterpret_cast<float2*>(&g_H[(size_t)row * TWO_DIM + col]) =
                    make_float2(acc[mf][nf][0], acc[mf][nf][1]);
            if (row + 8 < B)
                *reinterpret_cast<float2*>(&g_H[(size_t)(row + 8) * TWO_DIM + col]) =
                    make_float2(acc[mf][nf][2], acc[mf][nf][3]);
        }
    }
}

// ---------------- Kernel 3: combine — cp.async double-buffered gather ----------
#define RPB 4
#define NTH 256
#define CHK 8                              // neighbors per chunk
// dynamic smem: 2 bufs x RPB rows x CHK nbrs x 64 threads x 16 B = 64 KB
#define CSMEM (2 * RPB * CHK * 64 * 16)

__global__ __launch_bounds__(NTH)
void combine(const int* __restrict__ nodes_u,
             const int* __restrict__ nodes_v,
             const int* __restrict__ neighbors,
             const int* __restrict__ neighbor_counts,
             const float* __restrict__ u2e,
             const float* __restrict__ v2e,
             const float* __restrict__ bvec,
             float* __restrict__ out,
             int B)
{
    extern __shared__ uint4 sbuf[];        // [2][RPB][CHK][64]
    __shared__ int   snb[RPB][KMAX];
    __shared__ int   scnt[RPB], su[RPB], svi[RPB], sbrow[RPB];
    __shared__ float sred[RPB][2];

    const int t    = threadIdx.x;
    const int gi   = t >> 6;               // group 0..3 -> row gi
    const int gt   = t & 63;
    const int c4   = gt * 4;
    const int row0 = blockIdx.x * RPB;

    if (t < RPB * KMAX) {
        int r = t >> 6, k = t & 63;
        int b = row0 + r; if (b >= B) b = B - 1;
        snb[r][k] = neighbors[(size_t)b * KMAX + k];
    }
    if (t < RPB) {
        int b = row0 + t; if (b >= B) b = B - 1;
        scnt[t]  = neighbor_counts[b];
        su[t]    = nodes_u[b];
        svi[t]   = nodes_v[b];
        sbrow[t] = b;
    }
    __syncthreads();

    const float4 b4 = *reinterpret_cast<const float4*>(&bvec[c4]);

    const int r   = gi;
    const int cnt = scnt[r];
    const float4 self4 = *reinterpret_cast<const float4*>(&u2e[(size_t)su[r]  * DIM + c4]);
    const float4 v4    = *reinterpret_cast<const float4*>(&v2e[(size_t)svi[r] * DIM + c4]);
    float partial;
    if (cnt > 0) {
        const size_t hb = (size_t)sbrow[r] * TWO_DIM;
        const float4 h1 = *reinterpret_cast<const float4*>(&g_H[hb + c4]);
        const float4 h2 = *reinterpret_cast<const float4*>(&g_H[hb + DIM + c4]);
        const int* nb = snb[r];
        // per-thread smem slot base (u32 shared address)
        const uint32_t sb0 = smem_u32(sbuf) + (uint32_t)(((r * CHK) * 64 + gt) * 16);
        const uint32_t bufstride = (uint32_t)(RPB * CHK * 64 * 16);
        const int nfull = cnt >> 3;        // full chunks of 8

        float4 a0 = make_float4(0, 0, 0, 0), a1 = a0;

        if (nfull > 0) {
            // prologue: chunk 0 -> buf 0
            #pragma unroll
            for (int j = 0; j < CHK; j++)
                CPA16(sb0 + j * 64 * 16, &u2e[(size_t)nb[j] * DIM + c4]);
            CPA_COMMIT();
            #pragma unroll 1
            for (int c = 1; c < nfull; c++) {
                const uint32_t dsty = sb0 + (c & 1) * bufstride;
                const int* nbc = nb + c * CHK;
                #pragma unroll
                for (int j = 0; j < CHK; j++)
                    CPA16(dsty + j * 64 * 16, &u2e[(size_t)nbc[j] * DIM + c4]);
                CPA_COMMIT();
                CPA_WAIT(1);               // chunk c-1 landed
                const uint4* src = reinterpret_cast<const uint4*>(
                    sbuf + ((size_t)((c - 1) & 1) * RPB * CHK * 64) + (size_t)r * CHK * 64 + gt);
                #pragma unroll
                for (int j = 0; j < CHK; j += 2) {
                    float4 x0 = *reinterpret_cast<const float4*>(&src[j * 64]);
                    float4 x1 = *reinterpret_cast<const float4*>(&src[(j + 1) * 64]);
                    a0.x += x0.x; a0.y += x0.y; a0.z += x0.z; a0.w += x0.w;
                    a1.x += x1.x; a1.y += x1.y; a1.z += x1.z; a1.w += x1.w;
                }
            }
            CPA_WAIT(0);                   // last chunk landed
            const uint4* src = reinterpret_cast<const uint4*>(
                sbuf + ((size_t)((nfull - 1) & 1) * RPB * CHK * 64) + (size_t)r * CHK * 64 + gt);
            #pragma unroll
            for (int j = 0; j < CHK; j += 2) {
                float4 x0 = *reinterpret_cast<const float4*>(&src[j * 64]);
                float4 x1 = *reinterpret_cast<const float4*>(&src[(j + 1) * 64]);
                a0.x += x0.x; a0.y += x0.y; a0.z += x0.z; a0.w += x0.w;
                a1.x += x1.x; a1.y += x1.y; a1.z += x1.z; a1.w += x1.w;
            }
        }
        // tail (cnt % 8) via direct loads, independent accumulators
        #pragma unroll 1
        for (int k = nfull * CHK; k < cnt; k++) {
            float4 x = *reinterpret_cast<const float4*>(&u2e[(size_t)nb[k] * DIM + c4]);
            a0.x += x.x; a0.y += x.y; a0.z += x.z; a0.w += x.w;
        }
        const float inv = 1.f / (float)cnt;
        float4 nm;
        nm.x = (a0.x + a1.x) * inv;
        nm.y = (a0.y + a1.y) * inv;
        nm.z = (a0.z + a1.z) * inv;
        nm.w = (a0.w + a1.w) * inv;
        partial = self4.x * h1.x + self4.y * h1.y + self4.z * h1.z + self4.w * h1.w
                + nm.x    * h2.x + nm.y    * h2.y + nm.z    * h2.z + nm.w    * h2.w
                + b4.x    * v4.x + b4.y    * v4.y + b4.z    * v4.z + b4.w    * v4.w;
    } else {
        partial = self4.x * v4.x + self4.y * v4.y + self4.z * v4.z + self4.w * v4.w;
    }
    #pragma unroll
    for (int o = 16; o; o >>= 1)
        partial += __shfl_down_sync(0xffffffffu, partial, o);
    if ((t & 31) == 0) sred[r][(t >> 5) & 1] = partial;
    __syncthreads();

    if (t < RPB) {
        float s = sred[t][0] + sred[t][1];
        if (row0 + t < B) out[row0 + t] = s;
    }
}

// ---------------- launch --------------------------------------------------------
extern "C" void kernel_launch(void* const* d_in, const int* in_sizes, int n_in,
                              void* d_out, int out_size)
{
    const int*   nodes_u         = (const int*)  d_in[0];
    const int*   nodes_v         = (const int*)  d_in[1];
    const int*   neighbors       = (const int*)  d_in[2];
    const int*   neighbor_counts = (const int*)  d_in[3];
    const float* u2e             = (const float*)d_in[4];
    const float* v2e             = (const float*)d_in[5];
    const float* W               = (const float*)d_in[6];
    const float* bvec            = (const float*)d_in[7];
    float*       out             = (float*)d_out;

    int B = in_sizes[0];
    if (B > B_MAX) B = B_MAX;
    const int nmt = (B + 15) / 16;

    cudaFuncSetAttribute(combine, cudaFuncAttributeMaxDynamicSharedMemorySize, CSMEM);

    conv_all<<<nmt + 128, 256>>>(W, nodes_v, v2e, B, nmt);
    dim3 ggrid((B + 127) / 128, TWO_DIM / 128);
    gemm_mma<<<ggrid, 256>>>(B);
    combine<<<(B + RPB - 1) / RPB, NTH, CSMEM>>>(nodes_u, nodes_v, neighbors,
                                                 neighbor_counts, u2e, v2e, bvec, out, B);
}